// round 6
// baseline (speedup 1.0000x reference)
#include <cuda_runtime.h>
#include <math.h>
#include <stdint.h>

#define BATCH 128
#define SEQ   256
#define HID   256
#define MROWS 32768
#define SC_NBLK 64

// ---------------- scratch (no allocations allowed) ----------------
__device__ float g_st1[(size_t)MROWS * 256];
__device__ float g_st2[(size_t)MROWS * 512];
__device__ float g_st3[(size_t)MROWS * 1024];
__device__ float g_u  [(size_t)MROWS * 1024];
__device__ float g_utr[(size_t)MROWS * 1024];   // [t][col 0..1023][b]
__device__ float g_hb[2][BATCH * HID];          // h double buffer [b][k]
__device__ float g_cb[2][BATCH * HID];          // c double buffer [b][k]
__device__ float g_w2t[512 * 256];              // se_w2^T  [512,256]
__device__ float g_w3t[1024 * 512];             // se_w3^T  [1024,512]
__device__ float g_uT [1024 * 2048];            // U_all_w^T [1024,2048]
__device__ unsigned g_bar_count;
__device__ unsigned g_bar_gen;

// ============================ PTX helpers (sm_80-class only) ===============
__device__ __forceinline__ uint32_t smem_u32(const void* p) {
    uint32_t a;
    asm("{ .reg .u64 t; cvta.to.shared.u64 t, %1; cvt.u32.u64 %0, t; }"
        : "=r"(a) : "l"(p));
    return a;
}
#define CP_ASYNC16(dst, src) \
    asm volatile("cp.async.cg.shared.global [%0], [%1], 16;" \
                 :: "r"(dst), "l"(src) : "memory")
#define CP_ASYNC_COMMIT() asm volatile("cp.async.commit_group;" ::: "memory")
#define CP_ASYNC_WAIT(n)  asm volatile("cp.async.wait_group %0;" ::"n"(n):"memory")

#define LDMX4(r, a) \
    asm volatile("ldmatrix.sync.aligned.m8n8.x4.shared.b16 {%0,%1,%2,%3}, [%4];" \
        : "=r"((r)[0]), "=r"((r)[1]), "=r"((r)[2]), "=r"((r)[3]) : "r"(a))
#define MMA_TF32(d, a, b) \
    asm volatile("mma.sync.aligned.m16n8k8.row.col.f32.tf32.tf32.f32 " \
        "{%0,%1,%2,%3},{%4,%5,%6,%7},{%8,%9},{%0,%1,%2,%3};" \
        : "+f"((d)[0]), "+f"((d)[1]), "+f"((d)[2]), "+f"((d)[3]) \
        : "r"((a)[0]), "r"((a)[1]), "r"((a)[2]), "r"((a)[3]), \
          "r"((b)[0]), "r"((b)[1]))

__device__ __forceinline__ uint32_t swz128(uint32_t off) {
    return off ^ ((off >> 3) & 0x70);
}
__device__ __forceinline__ float tf32_rna(float x) {
    uint32_t b;
    asm("cvt.rna.tf32.f32 %0, %1;" : "=r"(b) : "f"(x));
    return __uint_as_float(b);
}

// ================= tf32 mma.sync GEMM: C[M,N] = [A1|A2] @ BT^T =============
#define STAGES 3
#define STAGE_BYTES 32768
#define MMA_SMEM (STAGES * STAGE_BYTES)

__global__ __launch_bounds__(256, 2)
void tc_gemm_kernel(const float* __restrict__ A1, int K1,
                    const float* __restrict__ A2, int K2,
                    const float* __restrict__ BT,
                    const float* __restrict__ bias,
                    float* __restrict__ C,
                    int M, int N, int Ktot, int relu)
{
    extern __shared__ char smc[];
    const uint32_t sbase = smem_u32(smc);
    const int tid  = threadIdx.x;
    const int wid  = tid >> 5, lane = tid & 31;
    const int n0   = blockIdx.x * 128;
    const int m0   = blockIdx.y * 128;
    const int NCH  = Ktot >> 5;
    const int wm   = wid & 1;
    const int wn   = wid >> 1;

    float acc[4][4][4];
#pragma unroll
    for (int mt = 0; mt < 4; mt++)
#pragma unroll
        for (int nt = 0; nt < 4; nt++)
#pragma unroll
            for (int q = 0; q < 4; q++) acc[mt][nt][q] = 0.f;

    auto load_chunk = [&](int stage, int k0) {
        uint32_t sA = sbase + stage * STAGE_BYTES;
        uint32_t sB = sA + 16384;
        const float* Ak; int kl;
        if (k0 < K1) { Ak = A1 + k0; kl = K1; }
        else         { Ak = A2 + (k0 - K1); kl = K2; }
#pragma unroll
        for (int q = 0; q < 4; q++) {
            int u = tid + 256 * q;
            int r = u >> 3, c = (u & 7) << 4;
            CP_ASYNC16(sA + swz128((uint32_t)(r * 128 + c)),
                       (const char*)(Ak + (size_t)(m0 + r) * kl) + c);
        }
#pragma unroll
        for (int q = 0; q < 4; q++) {
            int u = tid + 256 * q;
            int r = u >> 3, c = (u & 7) << 4;
            CP_ASYNC16(sB + swz128((uint32_t)(r * 128 + c)),
                       (const char*)(BT + (size_t)(n0 + r) * Ktot + k0) + c);
        }
        CP_ASYNC_COMMIT();
    };

    load_chunk(0, 0);
    load_chunk(1, 32);

    const int arow_l = (lane & 15);
    const int akb_l  = (lane >> 4) << 4;
    const int brow_l = (lane & 7);
    const int bqb_l  = (lane >> 3) << 4;

    for (int i = 0; i < NCH; i++) {
        if (i < NCH - 1) { CP_ASYNC_WAIT(1); }
        else             { CP_ASYNC_WAIT(0); }
        __syncthreads();

        const int j = i + STAGES - 1;
        if (j < NCH) load_chunk(j % STAGES, j * 32);

        uint32_t sA = sbase + (i % STAGES) * STAGE_BYTES;
        uint32_t sB = sA + 16384;

#pragma unroll
        for (int s2 = 0; s2 < 2; s2++) {
            uint32_t bfr4[4][4];
#pragma unroll
            for (int nt = 0; nt < 4; nt++) {
                int row = wn * 32 + nt * 8 + brow_l;
                LDMX4(bfr4[nt], sB + swz128((uint32_t)(row * 128 + s2 * 64 + bqb_l)));
            }
#pragma unroll
            for (int sh = 0; sh < 2; sh++) {
#pragma unroll
                for (int mt = 0; mt < 4; mt++) {
                    uint32_t afr[4];
                    int row = wm * 64 + mt * 16 + arow_l;
                    LDMX4(afr, sA + swz128((uint32_t)(row * 128 + (s2 * 2 + sh) * 32 + akb_l)));
#pragma unroll
                    for (int nt = 0; nt < 4; nt++)
                        MMA_TF32(acc[mt][nt], afr, &bfr4[nt][sh * 2]);
                }
            }
        }
        __syncthreads();
    }

    const int mbase = m0 + wm * 64;
    const int nbase = n0 + wn * 32;
    const int cc = (lane & 3) * 2;
    const int rr = lane >> 2;
    float bx[4], by[4];
#pragma unroll
    for (int nt = 0; nt < 4; nt++) {
        bx[nt] = bias[nbase + nt * 8 + cc];
        by[nt] = bias[nbase + nt * 8 + cc + 1];
    }
#pragma unroll
    for (int mt = 0; mt < 4; mt++) {
        int r0 = mbase + mt * 16 + rr;
#pragma unroll
        for (int nt = 0; nt < 4; nt++) {
            int c0 = nbase + nt * 8 + cc;
            float v0 = acc[mt][nt][0] + bx[nt];
            float v1 = acc[mt][nt][1] + by[nt];
            float v2 = acc[mt][nt][2] + bx[nt];
            float v3 = acc[mt][nt][3] + by[nt];
            if (relu) {
                v0 = fmaxf(v0, 0.f); v1 = fmaxf(v1, 0.f);
                v2 = fmaxf(v2, 0.f); v3 = fmaxf(v3, 0.f);
            }
            *(float2*)(C + (size_t)r0 * N + c0) = make_float2(v0, v1);
            *(float2*)(C + (size_t)(r0 + 8) * N + c0) = make_float2(v2, v3);
        }
    }
}

// ---------------- weight transposes: [R,C] -> [C,R] ------------------------
__global__ void wtrans_kernel(const float* __restrict__ w2,
                              const float* __restrict__ w3,
                              const float* __restrict__ uw)
{
    const float* in; float* out; int R, C;
    if (blockIdx.z == 0)      { in = w2; out = g_w2t; R = 256;  C = 512;  }
    else if (blockIdx.z == 1) { in = w3; out = g_w3t; R = 512;  C = 1024; }
    else                      { in = uw; out = g_uT;  R = 2048; C = 1024; }
    if ((int)blockIdx.x * 32 >= C || (int)blockIdx.y * 32 >= R) return;
    __shared__ float t[32][33];
    const int tx = threadIdx.x, ty = threadIdx.y;
#pragma unroll
    for (int i = 0; i < 4; i++) {
        int r = blockIdx.y * 32 + ty + i * 8;
        int c = blockIdx.x * 32 + tx;
        t[ty + i * 8][tx] = in[(size_t)r * C + c];
    }
    __syncthreads();
#pragma unroll
    for (int i = 0; i < 4; i++) {
        int c = blockIdx.x * 32 + ty + i * 8;
        int r = blockIdx.y * 32 + tx;
        out[(size_t)c * R + r] = t[tx][ty + i * 8];
    }
}

// ---------------- SIMT SGEMM (se1 only, K=67) ------------------------------
__global__ __launch_bounds__(256, 2) void sgemm_kernel(
    const float* __restrict__ A, const float* __restrict__ B,
    const float* __restrict__ bias, float* __restrict__ C,
    int M, int N, int K, int relu)
{
    __shared__ float As[8][128];
    __shared__ float Bs[8][128];
    const int tid = threadIdx.x;
    const int tx = tid & 15, ty = tid >> 4;
    const float* Ab = A + (size_t)blockIdx.y * 128 * K;
    const float* Bb = B + blockIdx.x * 128;

    float acc[8][8];
#pragma unroll
    for (int i = 0; i < 8; i++)
#pragma unroll
        for (int j = 0; j < 8; j++) acc[i][j] = 0.f;

    const int aRow = tid >> 1, aCol = (tid & 1) << 2;
    const int bRow = tid >> 5, bCol = (tid & 31) << 2;

    for (int k0 = 0; k0 < K; k0 += 8) {
#pragma unroll
        for (int i2 = 0; i2 < 4; i2++) {
            int kk = aCol + i2;
            As[kk][aRow] = (k0 + kk < K) ? Ab[(size_t)aRow * K + k0 + kk] : 0.f;
        }
        if (k0 + bRow < K) {
            float4 bv = *(const float4*)(Bb + (size_t)(k0 + bRow) * N + bCol);
            Bs[bRow][bCol + 0] = bv.x; Bs[bRow][bCol + 1] = bv.y;
            Bs[bRow][bCol + 2] = bv.z; Bs[bRow][bCol + 3] = bv.w;
        } else {
            Bs[bRow][bCol + 0] = 0.f; Bs[bRow][bCol + 1] = 0.f;
            Bs[bRow][bCol + 2] = 0.f; Bs[bRow][bCol + 3] = 0.f;
        }
        __syncthreads();
#pragma unroll
        for (int kk = 0; kk < 8; kk++) {
            float av[8], bv[8];
#pragma unroll
            for (int i = 0; i < 8; i++) av[i] = As[kk][ty * 8 + i];
#pragma unroll
            for (int j = 0; j < 8; j++) bv[j] = Bs[kk][tx * 8 + j];
#pragma unroll
            for (int i = 0; i < 8; i++)
#pragma unroll
                for (int j = 0; j < 8; j++)
                    acc[i][j] += av[i] * bv[j];
        }
        __syncthreads();
    }

    const int row0 = blockIdx.y * 128 + ty * 8;
    const int col0 = blockIdx.x * 128 + tx * 8;
#pragma unroll
    for (int i = 0; i < 8; i++) {
        float* Cp = C + (size_t)(row0 + i) * N + col0;
#pragma unroll
        for (int j = 0; j < 8; j++) {
            float v = acc[i][j] + bias[col0 + j];
            if (relu) v = fmaxf(v, 0.f);
            Cp[j] = v;
        }
    }
}

// ---------------- transpose u[(b*SEQ+t)*1024+n] -> g_utr[(t*1024+n)*128+b] --
__global__ void transpose_u_kernel(const float* __restrict__ u)
{
    __shared__ float tile[32][33];
    const int nt = blockIdx.x;
    const int t  = blockIdx.y;
    const int bt = blockIdx.z;
    const int tx = threadIdx.x, ty = threadIdx.y;
#pragma unroll
    for (int i = 0; i < 4; i++) {
        int b = bt * 32 + ty + i * 8;
        int n = nt * 32 + tx;
        tile[ty + i * 8][tx] = u[((size_t)(b * SEQ + t)) * 1024 + n];
    }
    __syncthreads();
#pragma unroll
    for (int i = 0; i < 4; i++) {
        int n = nt * 32 + ty + i * 8;
        int b = bt * 32 + tx;
        g_utr[((size_t)t * 1024 + n) * 128 + b] = tile[tx][ty + i * 8];
    }
}

__global__ void barinit_kernel() { g_bar_count = 0u; g_bar_gen = 0u; }

__device__ __forceinline__ void grid_barrier(unsigned gen)
{
    __syncthreads();
    if (threadIdx.x == 0) {
        __threadfence();
        unsigned arrived = atomicAdd(&g_bar_count, 1u) + 1u;
        if (arrived == gen * SC_NBLK) {
            __threadfence();
            *(volatile unsigned*)&g_bar_gen = gen;
        } else {
            while (*(volatile unsigned*)&g_bar_gen < gen) { __nanosleep(32); }
        }
        __threadfence();
    }
    __syncthreads();
}

__device__ __forceinline__ float sigf(float x) { return 1.f / (1.f + __expf(-x)); }

// ================= tensor-core persistent TLSTM scan =======================
// 64 blocks x 256 threads. Block = (mh = batch half, jgrp = 8 features).
// Weights (4 gates + W_d cols, hi/lo tf32 split) resident in smem.
// Per step: cp.async h/c slice, 3xTF32 mma, smem exchange, pointwise, barrier.
#define OFF_WHI 0
#define OFF_WLO 40960
#define OFF_H   81920
#define OFF_C   147456
#define OFF_EX  212992
#define OFF_BI  223232
#define SC_SMEM 223424

__global__ __launch_bounds__(256, 1) void scan_tc_kernel(
    const float* __restrict__ ts,
    const float* __restrict__ W_all, const float* __restrict__ W_all_b,
    const float* __restrict__ W_d,   const float* __restrict__ W_d_b,
    float* __restrict__ feat)
{
    extern __shared__ char smc[];
    const uint32_t sb = smem_u32(smc);
    float* Ex = (float*)(smc + OFF_EX);
    float* Bi = (float*)(smc + OFF_BI);
    const int tid  = threadIdx.x;
    const int lane = tid & 31, wid = tid >> 5;
    const int mh   = blockIdx.x & 1;
    const int j0   = (blockIdx.x >> 1) * 8;

    // ---- stage weights hi/lo (once) ----
    for (int idx = tid; idx < 10240; idx += 256) {
        int n = idx >> 8, k = idx & 255;
        int g = n >> 3, jj = n & 7;
        float w = (g < 4) ? W_all[k * 1024 + g * 256 + j0 + jj]
                          : W_d[k * 256 + j0 + jj];
        float hi = tf32_rna(w);
        float lo = w - hi;
        uint32_t off = (uint32_t)((k >> 5) * 5120)
                     + swz128((uint32_t)(n * 128 + (k & 31) * 4));
        *(float*)(smc + OFF_WHI + off) = hi;
        *(float*)(smc + OFF_WLO + off) = lo;
    }
    if (tid < 40) {
        int g = tid >> 3, jj = tid & 7;
        Bi[tid] = (g < 4) ? W_all_b[g * 256 + j0 + jj] : W_d_b[j0 + jj];
    }
    // zero h0/c0 (parity 0)
    for (int idx = blockIdx.x * 256 + tid; idx < BATCH * HID; idx += SC_NBLK * 256) {
        g_hb[0][idx] = 0.f;
        g_cb[0][idx] = 0.f;
    }
    grid_barrier(1);

    const int mt = wid & 3, setid = wid >> 2;
    const uint32_t a_off = (uint32_t)((mt * 16 + (lane & 15)) * 128)
                         + (uint32_t)((lane >> 4) << 4);
    const int g_base = (setid == 0) ? 0 : 2;
    const int n_grp  = (setid == 0) ? 2 : 3;

    for (int t = 0; t < SEQ; t++) {
        // ---- stage h/c slice ----
        const float* hsrc = &g_hb[t & 1][mh * 64 * 256];
        const float* csrc = &g_cb[t & 1][mh * 64 * 256];
#pragma unroll
        for (int i = 0; i < 16; i++) {
            int idx = tid + i * 256;
            int r = idx >> 6, kq = idx & 63;
            uint32_t d = (uint32_t)((kq >> 3) * 8192)
                       + swz128((uint32_t)(r * 128 + (kq & 7) * 16));
            CP_ASYNC16(sb + OFF_H + d, (const char*)(hsrc + r * 256 + kq * 4));
            CP_ASYNC16(sb + OFF_C + d, (const char*)(csrc + r * 256 + kq * 4));
        }
        CP_ASYNC_COMMIT();
        CP_ASYNC_WAIT(0);
        __syncthreads();

        // ---- 3xTF32 MMA ----
        float acc[3][4];
#pragma unroll
        for (int gi = 0; gi < 3; gi++)
#pragma unroll
            for (int q = 0; q < 4; q++) acc[gi][q] = 0.f;

#pragma unroll 2
        for (int kb = 0; kb < 8; kb++) {
            uint32_t wb = (uint32_t)(kb * 5120);
            uint32_t hb = sb + OFF_H + kb * 8192;
            uint32_t cb = sb + OFF_C + kb * 8192;
#pragma unroll
            for (int s2 = 0; s2 < 2; s2++) {
                uint32_t bh[3][4], bl[3][4];
#pragma unroll
                for (int gi = 0; gi < 3; gi++) {
                    if (gi < n_grp) {
                        int g = g_base + gi;
                        uint32_t boff = wb + swz128(
                            (uint32_t)((g * 8 + (lane & 7)) * 128 + s2 * 64
                                       + ((lane >> 3) << 4)));
                        LDMX4(bh[gi], sb + OFF_WHI + boff);
                        LDMX4(bl[gi], sb + OFF_WLO + boff);
                    }
                }
#pragma unroll
                for (int sh = 0; sh < 2; sh++) {
                    uint32_t sbyte = (uint32_t)((s2 * 2 + sh) * 32);
                    uint32_t ar[4], ahi[4], alo[4];
                    LDMX4(ar, hb + ((a_off + sbyte) ^ (((a_off + sbyte) >> 3) & 0x70)));
#pragma unroll
                    for (int q = 0; q < 4; q++) {
                        float f = __uint_as_float(ar[q]);
                        float h = tf32_rna(f);
                        ahi[q] = __float_as_uint(h);
                        alo[q] = __float_as_uint(f - h);
                    }
                    uint32_t chi[4], clo[4];
                    if (setid == 1) {
                        uint32_t cr[4];
                        LDMX4(cr, cb + ((a_off + sbyte) ^ (((a_off + sbyte) >> 3) & 0x70)));
#pragma unroll
                        for (int q = 0; q < 4; q++) {
                            float f = __uint_as_float(cr[q]);
                            float h = tf32_rna(f);
                            chi[q] = __float_as_uint(h);
                            clo[q] = __float_as_uint(f - h);
                        }
                    }
#pragma unroll
                    for (int gi = 0; gi < 3; gi++) {
                        if (gi < n_grp) {
                            bool use_c = (setid == 1) && (gi == 2);
                            uint32_t* Ahi = use_c ? chi : ahi;
                            uint32_t* Alo = use_c ? clo : alo;
                            MMA_TF32(acc[gi], Ahi, &bh[gi][sh * 2]);
                            MMA_TF32(acc[gi], Ahi, &bl[gi][sh * 2]);
                            MMA_TF32(acc[gi], Alo, &bh[gi][sh * 2]);
                        }
                    }
                }
            }
        }

        // ---- exchange accumulators through smem ----
#pragma unroll
        for (int gi = 0; gi < 3; gi++) {
            if (gi < n_grp) {
                int g = g_base + gi;
#pragma unroll
                for (int q = 0; q < 4; q++) {
                    int row = mt * 16 + (lane >> 2) + ((q >> 1) << 3);
                    int j = ((lane & 3) << 1) + (q & 1);
                    Ex[(g * 64 + row) * 8 + j] = acc[gi][q];
                }
            }
        }
        __syncthreads();

        // ---- pointwise update: thread -> (row, 2 features) ----
        {
            int row = tid >> 2;
            int b = mh * 64 + row;
            float tt = ts[b * SEQ + t];
            float* hout = &g_hb[(t + 1) & 1][b * 256];
            float* cout = &g_cb[(t + 1) & 1][b * 256];
            float* fout = &feat[((size_t)b * SEQ + t) * 256];
#pragma unroll
            for (int e = 0; e < 2; e++) {
                int j = (tid & 3) * 2 + e;
                int jg = j0 + j;
                float s0 = Ex[(0 * 64 + row) * 8 + j] + Bi[0 + j];
                float s1 = Ex[(1 * 64 + row) * 8 + j] + Bi[8 + j];
                float s2v = Ex[(2 * 64 + row) * 8 + j] + Bi[16 + j];
                float s3 = Ex[(3 * 64 + row) * 8 + j] + Bi[24 + j];
                float s4 = Ex[(4 * 64 + row) * 8 + j] + Bi[32 + j];
                const float* up = g_utr + ((size_t)t * 1024 + jg) * 128 + b;
                float f  = sigf(s0 + up[0]);
                float ii = sigf(s1 + up[256 * 128]);
                float o  = sigf(s2v + up[512 * 128]);
                float ct = sigf(s3 + up[768 * 128]);
                float d  = tanhf(s4);
                uint32_t coff = (uint32_t)((jg >> 5) * 8192)
                              + swz128((uint32_t)(row * 128 + (jg & 31) * 4));
                float cprev = *(float*)(smc + OFF_C + coff);
                float c_adj = (cprev - d) + d * tt;
                float cn = f * c_adj + ii * ct;
                float hn = o * tanhf(cn);
                hout[jg] = hn;
                cout[jg] = cn;
                fout[jg] = hn;
            }
        }
        grid_barrier((unsigned)(t + 2));
    }
}

// ---------------- classifier ----------------------------------------------
__global__ void cls_kernel(const float* __restrict__ feat,
                           const float* __restrict__ w,
                           const float* __restrict__ bias,
                           float* __restrict__ out)
{
    int lane = threadIdx.x & 31;
    int wrow = (blockIdx.x * blockDim.x + threadIdx.x) >> 5;
    if (wrow >= MROWS) return;
    const float* fr = feat + (size_t)wrow * HID;
    float s = 0.f;
#pragma unroll
    for (int i = 0; i < 8; i++) s += fr[lane + 32 * i] * w[lane + 32 * i];
#pragma unroll
    for (int off = 16; off > 0; off >>= 1)
        s += __shfl_down_sync(0xffffffffu, s, off);
    if (lane == 0) out[wrow] = s + bias[0];
}

// ---------------------------------------------------------------------------
extern "C" void kernel_launch(void* const* d_in, const int* in_sizes, int n_in,
                              void* d_out, int out_size)
{
    const float* x       = (const float*)d_in[0];
    const float* stages  = (const float*)d_in[1];
    const float* tsmp    = (const float*)d_in[2];
    const float* se_w1   = (const float*)d_in[3];
    const float* se_b1   = (const float*)d_in[4];
    const float* se_w2   = (const float*)d_in[5];
    const float* se_b2   = (const float*)d_in[6];
    const float* se_w3   = (const float*)d_in[7];
    const float* se_b3   = (const float*)d_in[8];
    const float* W_all_w = (const float*)d_in[9];
    const float* W_all_b = (const float*)d_in[10];
    const float* U_all_w = (const float*)d_in[11];
    const float* U_all_b = (const float*)d_in[12];
    const float* W_d_w   = (const float*)d_in[13];
    const float* W_d_b   = (const float*)d_in[14];
    const float* cls_w   = (const float*)d_in[15];
    const float* cls_b   = (const float*)d_in[16];

    float* out  = (float*)d_out;
    float* feat = out + MROWS;

    void *p_st1, *p_st2, *p_st3, *p_u, *p_w2t, *p_w3t, *p_uT;
    cudaGetSymbolAddress(&p_st1, g_st1);
    cudaGetSymbolAddress(&p_st2, g_st2);
    cudaGetSymbolAddress(&p_st3, g_st3);
    cudaGetSymbolAddress(&p_u,   g_u);
    cudaGetSymbolAddress(&p_w2t, g_w2t);
    cudaGetSymbolAddress(&p_w3t, g_w3t);
    cudaGetSymbolAddress(&p_uT,  g_uT);
    float* st1 = (float*)p_st1;
    float* st2 = (float*)p_st2;
    float* st3 = (float*)p_st3;
    float* u   = (float*)p_u;
    float* w2t = (float*)p_w2t;
    float* w3t = (float*)p_w3t;
    float* uT  = (float*)p_uT;

    cudaFuncSetAttribute(tc_gemm_kernel,
                         cudaFuncAttributeMaxDynamicSharedMemorySize, MMA_SMEM);
    cudaFuncSetAttribute(scan_tc_kernel,
                         cudaFuncAttributeMaxDynamicSharedMemorySize, SC_SMEM);

    // 1. transpose weights to K-major
    wtrans_kernel<<<dim3(32, 64, 3), dim3(32, 8)>>>(se_w2, se_w3, U_all_w);
    // 2. barrier reset
    barinit_kernel<<<1, 1>>>();
    // 3. se1 (K=67) SIMT
    sgemm_kernel<<<dim3(2, 256), 256>>>(stages, se_w1, se_b1, st1,
                                        MROWS, 256, 67, 1);
    // 4. se2
    tc_gemm_kernel<<<dim3(4, 256), 256, MMA_SMEM>>>(
        st1, 256, st1, 256, w2t, se_b2, st2, MROWS, 512, 256, 1);
    // 5. se3
    tc_gemm_kernel<<<dim3(8, 256), 256, MMA_SMEM>>>(
        st2, 512, st2, 512, w3t, se_b3, st3, MROWS, 1024, 512, 1);
    // 6. uproj fused K=2048
    tc_gemm_kernel<<<dim3(8, 256), 256, MMA_SMEM>>>(
        x, 1024, st3, 1024, uT, U_all_b, u, MROWS, 1024, 2048, 0);
    // 7. transpose u to [t][col][b]
    transpose_u_kernel<<<dim3(32, 256, 4), dim3(32, 8)>>>(u);
    // 8. tensor-core persistent scan
    scan_tc_kernel<<<SC_NBLK, 256, SC_SMEM>>>(tsmp, W_all_w, W_all_b,
                                              W_d_w, W_d_b, feat);
    // 9. classifier
    cls_kernel<<<4096, 256>>>(feat, cls_w, cls_b, out);
}

// round 7
// speedup vs baseline: 1.4537x; 1.4537x over previous
#include <cuda_runtime.h>
#include <math.h>
#include <stdint.h>

#define BATCH 128
#define SEQ   256
#define HID   256
#define MROWS 32768
#define SC2_NBLK 128

// ---------------- scratch (no allocations allowed) ----------------
__device__ float g_st1[(size_t)MROWS * 256];
__device__ float g_st2[(size_t)MROWS * 512];
__device__ float g_st3[(size_t)MROWS * 1024];
__device__ float g_u  [(size_t)MROWS * 1024];
__device__ float g_utr[(size_t)MROWS * 1024];   // [t][col 0..1023][b]
__device__ float g_hc[2][2][HID * BATCH];       // [buf][h=0/c=1][k*128+b]
__device__ float g_w2t[512 * 256];              // se_w2^T  [512,256]
__device__ float g_w3t[1024 * 512];             // se_w3^T  [1024,512]
__device__ float g_uT [1024 * 2048];            // U_all_w^T [1024,2048]
__device__ unsigned g_bar_count;
__device__ unsigned g_bar_gen;

// ============================ PTX helpers (sm_80/sm_100 base, no 'a') ======
__device__ __forceinline__ uint32_t smem_u32(const void* p) {
    uint32_t a;
    asm("{ .reg .u64 t; cvta.to.shared.u64 t, %1; cvt.u32.u64 %0, t; }"
        : "=r"(a) : "l"(p));
    return a;
}
#define CP_ASYNC16(dst, src) \
    asm volatile("cp.async.cg.shared.global [%0], [%1], 16;" \
                 :: "r"(dst), "l"(src) : "memory")
#define CP_ASYNC_COMMIT() asm volatile("cp.async.commit_group;" ::: "memory")
#define CP_ASYNC_WAIT(n)  asm volatile("cp.async.wait_group %0;" ::"n"(n):"memory")

#define LDMX4(r, a) \
    asm volatile("ldmatrix.sync.aligned.m8n8.x4.shared.b16 {%0,%1,%2,%3}, [%4];" \
        : "=r"((r)[0]), "=r"((r)[1]), "=r"((r)[2]), "=r"((r)[3]) : "r"(a))
#define MMA_TF32(d, a, b) \
    asm volatile("mma.sync.aligned.m16n8k8.row.col.f32.tf32.tf32.f32 " \
        "{%0,%1,%2,%3},{%4,%5,%6,%7},{%8,%9},{%0,%1,%2,%3};" \
        : "+f"((d)[0]), "+f"((d)[1]), "+f"((d)[2]), "+f"((d)[3]) \
        : "r"((a)[0]), "r"((a)[1]), "r"((a)[2]), "r"((a)[3]), \
          "r"((b)[0]), "r"((b)[1]))

__device__ __forceinline__ uint32_t swz128(uint32_t off) {
    return off ^ ((off >> 3) & 0x70);
}
// packed f32x2 (Blackwell base feature, sm_100+, not arch-'a'-gated)
__device__ __forceinline__ uint64_t pk2(float lo, float hi) {
    uint64_t r;
    asm("mov.b64 %0, {%1, %2};" : "=l"(r) : "f"(lo), "f"(hi));
    return r;
}
__device__ __forceinline__ float2 upk2(uint64_t v) {
    float2 f;
    asm("mov.b64 {%0, %1}, %2;" : "=f"(f.x), "=f"(f.y) : "l"(v));
    return f;
}
__device__ __forceinline__ uint64_t ffma2(uint64_t a, uint64_t b, uint64_t c) {
    uint64_t d;
    asm("fma.rn.f32x2 %0, %1, %2, %3;" : "=l"(d) : "l"(a), "l"(b), "l"(c));
    return d;
}

// ================= tf32 mma.sync GEMM: C[M,N] = [A1|A2] @ BT^T =============
#define STAGES 3
#define STAGE_BYTES 32768
#define MMA_SMEM (STAGES * STAGE_BYTES)

__global__ __launch_bounds__(256, 2)
void tc_gemm_kernel(const float* __restrict__ A1, int K1,
                    const float* __restrict__ A2, int K2,
                    const float* __restrict__ BT,
                    const float* __restrict__ bias,
                    float* __restrict__ C,
                    int M, int N, int Ktot, int relu)
{
    extern __shared__ char smc[];
    const uint32_t sbase = smem_u32(smc);
    const int tid  = threadIdx.x;
    const int wid  = tid >> 5, lane = tid & 31;
    const int n0   = blockIdx.x * 128;
    const int m0   = blockIdx.y * 128;
    const int NCH  = Ktot >> 5;
    const int wm   = wid & 1;
    const int wn   = wid >> 1;

    float acc[4][4][4];
#pragma unroll
    for (int mt = 0; mt < 4; mt++)
#pragma unroll
        for (int nt = 0; nt < 4; nt++)
#pragma unroll
            for (int q = 0; q < 4; q++) acc[mt][nt][q] = 0.f;

    auto load_chunk = [&](int stage, int k0) {
        uint32_t sA = sbase + stage * STAGE_BYTES;
        uint32_t sB = sA + 16384;
        const float* Ak; int kl;
        if (k0 < K1) { Ak = A1 + k0; kl = K1; }
        else         { Ak = A2 + (k0 - K1); kl = K2; }
#pragma unroll
        for (int q = 0; q < 4; q++) {
            int u = tid + 256 * q;
            int r = u >> 3, c = (u & 7) << 4;
            CP_ASYNC16(sA + swz128((uint32_t)(r * 128 + c)),
                       (const char*)(Ak + (size_t)(m0 + r) * kl) + c);
        }
#pragma unroll
        for (int q = 0; q < 4; q++) {
            int u = tid + 256 * q;
            int r = u >> 3, c = (u & 7) << 4;
            CP_ASYNC16(sB + swz128((uint32_t)(r * 128 + c)),
                       (const char*)(BT + (size_t)(n0 + r) * Ktot + k0) + c);
        }
        CP_ASYNC_COMMIT();
    };

    load_chunk(0, 0);
    load_chunk(1, 32);

    const int arow_l = (lane & 15);
    const int akb_l  = (lane >> 4) << 4;
    const int brow_l = (lane & 7);
    const int bqb_l  = (lane >> 3) << 4;

    for (int i = 0; i < NCH; i++) {
        if (i < NCH - 1) { CP_ASYNC_WAIT(1); }
        else             { CP_ASYNC_WAIT(0); }
        __syncthreads();

        const int j = i + STAGES - 1;
        if (j < NCH) load_chunk(j % STAGES, j * 32);

        uint32_t sA = sbase + (i % STAGES) * STAGE_BYTES;
        uint32_t sB = sA + 16384;

#pragma unroll
        for (int s2 = 0; s2 < 2; s2++) {
            uint32_t bfr4[4][4];
#pragma unroll
            for (int nt = 0; nt < 4; nt++) {
                int row = wn * 32 + nt * 8 + brow_l;
                LDMX4(bfr4[nt], sB + swz128((uint32_t)(row * 128 + s2 * 64 + bqb_l)));
            }
#pragma unroll
            for (int sh = 0; sh < 2; sh++) {
#pragma unroll
                for (int mt = 0; mt < 4; mt++) {
                    uint32_t afr[4];
                    int row = wm * 64 + mt * 16 + arow_l;
                    LDMX4(afr, sA + swz128((uint32_t)(row * 128 + (s2 * 2 + sh) * 32 + akb_l)));
#pragma unroll
                    for (int nt = 0; nt < 4; nt++)
                        MMA_TF32(acc[mt][nt], afr, &bfr4[nt][sh * 2]);
                }
            }
        }
        __syncthreads();
    }

    const int mbase = m0 + wm * 64;
    const int nbase = n0 + wn * 32;
    const int cc = (lane & 3) * 2;
    const int rr = lane >> 2;
    float bx[4], by[4];
#pragma unroll
    for (int nt = 0; nt < 4; nt++) {
        bx[nt] = bias[nbase + nt * 8 + cc];
        by[nt] = bias[nbase + nt * 8 + cc + 1];
    }
#pragma unroll
    for (int mt = 0; mt < 4; mt++) {
        int r0 = mbase + mt * 16 + rr;
#pragma unroll
        for (int nt = 0; nt < 4; nt++) {
            int c0 = nbase + nt * 8 + cc;
            float v0 = acc[mt][nt][0] + bx[nt];
            float v1 = acc[mt][nt][1] + by[nt];
            float v2 = acc[mt][nt][2] + bx[nt];
            float v3 = acc[mt][nt][3] + by[nt];
            if (relu) {
                v0 = fmaxf(v0, 0.f); v1 = fmaxf(v1, 0.f);
                v2 = fmaxf(v2, 0.f); v3 = fmaxf(v3, 0.f);
            }
            *(float2*)(C + (size_t)r0 * N + c0) = make_float2(v0, v1);
            *(float2*)(C + (size_t)(r0 + 8) * N + c0) = make_float2(v2, v3);
        }
    }
}

// ---------------- weight transposes: [R,C] -> [C,R] ------------------------
__global__ void wtrans_kernel(const float* __restrict__ w2,
                              const float* __restrict__ w3,
                              const float* __restrict__ uw)
{
    const float* in; float* out; int R, C;
    if (blockIdx.z == 0)      { in = w2; out = g_w2t; R = 256;  C = 512;  }
    else if (blockIdx.z == 1) { in = w3; out = g_w3t; R = 512;  C = 1024; }
    else                      { in = uw; out = g_uT;  R = 2048; C = 1024; }
    if ((int)blockIdx.x * 32 >= C || (int)blockIdx.y * 32 >= R) return;
    __shared__ float t[32][33];
    const int tx = threadIdx.x, ty = threadIdx.y;
#pragma unroll
    for (int i = 0; i < 4; i++) {
        int r = blockIdx.y * 32 + ty + i * 8;
        int c = blockIdx.x * 32 + tx;
        t[ty + i * 8][tx] = in[(size_t)r * C + c];
    }
    __syncthreads();
#pragma unroll
    for (int i = 0; i < 4; i++) {
        int c = blockIdx.x * 32 + ty + i * 8;
        int r = blockIdx.y * 32 + tx;
        out[(size_t)c * R + r] = t[tx][ty + i * 8];
    }
}

// ---------------- SIMT SGEMM (se1 only, K=67) ------------------------------
__global__ __launch_bounds__(256, 2) void sgemm_kernel(
    const float* __restrict__ A, const float* __restrict__ B,
    const float* __restrict__ bias, float* __restrict__ C,
    int M, int N, int K, int relu)
{
    __shared__ float As[8][128];
    __shared__ float Bs[8][128];
    const int tid = threadIdx.x;
    const int tx = tid & 15, ty = tid >> 4;
    const float* Ab = A + (size_t)blockIdx.y * 128 * K;
    const float* Bb = B + blockIdx.x * 128;

    float acc[8][8];
#pragma unroll
    for (int i = 0; i < 8; i++)
#pragma unroll
        for (int j = 0; j < 8; j++) acc[i][j] = 0.f;

    const int aRow = tid >> 1, aCol = (tid & 1) << 2;
    const int bRow = tid >> 5, bCol = (tid & 31) << 2;

    for (int k0 = 0; k0 < K; k0 += 8) {
#pragma unroll
        for (int i2 = 0; i2 < 4; i2++) {
            int kk = aCol + i2;
            As[kk][aRow] = (k0 + kk < K) ? Ab[(size_t)aRow * K + k0 + kk] : 0.f;
        }
        if (k0 + bRow < K) {
            float4 bv = *(const float4*)(Bb + (size_t)(k0 + bRow) * N + bCol);
            Bs[bRow][bCol + 0] = bv.x; Bs[bRow][bCol + 1] = bv.y;
            Bs[bRow][bCol + 2] = bv.z; Bs[bRow][bCol + 3] = bv.w;
        } else {
            Bs[bRow][bCol + 0] = 0.f; Bs[bRow][bCol + 1] = 0.f;
            Bs[bRow][bCol + 2] = 0.f; Bs[bRow][bCol + 3] = 0.f;
        }
        __syncthreads();
#pragma unroll
        for (int kk = 0; kk < 8; kk++) {
            float av[8], bv[8];
#pragma unroll
            for (int i = 0; i < 8; i++) av[i] = As[kk][ty * 8 + i];
#pragma unroll
            for (int j = 0; j < 8; j++) bv[j] = Bs[kk][tx * 8 + j];
#pragma unroll
            for (int i = 0; i < 8; i++)
#pragma unroll
                for (int j = 0; j < 8; j++)
                    acc[i][j] += av[i] * bv[j];
        }
        __syncthreads();
    }

    const int row0 = blockIdx.y * 128 + ty * 8;
    const int col0 = blockIdx.x * 128 + tx * 8;
#pragma unroll
    for (int i = 0; i < 8; i++) {
        float* Cp = C + (size_t)(row0 + i) * N + col0;
#pragma unroll
        for (int j = 0; j < 8; j++) {
            float v = acc[i][j] + bias[col0 + j];
            if (relu) v = fmaxf(v, 0.f);
            Cp[j] = v;
        }
    }
}

// ---------------- transpose u[(b*SEQ+t)*1024+n] -> g_utr[(t*1024+n)*128+b] --
__global__ void transpose_u_kernel(const float* __restrict__ u)
{
    __shared__ float tile[32][33];
    const int nt = blockIdx.x;
    const int t  = blockIdx.y;
    const int bt = blockIdx.z;
    const int tx = threadIdx.x, ty = threadIdx.y;
#pragma unroll
    for (int i = 0; i < 4; i++) {
        int b = bt * 32 + ty + i * 8;
        int n = nt * 32 + tx;
        tile[ty + i * 8][tx] = u[((size_t)(b * SEQ + t)) * 1024 + n];
    }
    __syncthreads();
#pragma unroll
    for (int i = 0; i < 4; i++) {
        int n = nt * 32 + ty + i * 8;
        int b = bt * 32 + tx;
        g_utr[((size_t)t * 1024 + n) * 128 + b] = tile[tx][ty + i * 8];
    }
}

__global__ void barinit_kernel() { g_bar_count = 0u; g_bar_gen = 0u; }

__device__ __forceinline__ void grid_barrier(unsigned gen)
{
    __syncthreads();
    if (threadIdx.x == 0) {
        __threadfence();
        unsigned arrived = atomicAdd(&g_bar_count, 1u) + 1u;
        if (arrived == gen * SC2_NBLK) {
            __threadfence();
            *(volatile unsigned*)&g_bar_gen = gen;
        } else {
            while (*(volatile unsigned*)&g_bar_gen < gen) { __nanosleep(32); }
        }
        __threadfence();
    }
    __syncthreads();
}

__device__ __forceinline__ float sigf(float x) { return 1.f / (1.f + __expf(-x)); }

// ================= persistent TLSTM scan v2 (SIMT + f32x2) =================
// 128 blocks = (64 j-quads) x (2 batch halves). Block: 4 features, 64 batch.
// Weights pre-duplicated as f32x2 pairs in smem (once). Thread = (warp=k-slice
// of 16, jp = feature pair, bq = 4-batch quad); h/c float4 load reused across
// 2 features; 20 FFMA2 per k. Partials [q][j][g][64b] -> STS.128, stride-1
// reduction. One grid barrier per step.
#define S2_WOFF 0                 // Wsm2: uint64 [256*4*5]   = 40960 B
#define S2_POFF 40960             // P:    float  [16*4*5*64] = 81920 B
#define S2_BOFF 122880            // Bi:   float  [20]
#define S2_SMEM 123008

__global__ __launch_bounds__(512, 1) void scan2_kernel(
    const float* __restrict__ ts,
    const float* __restrict__ W_all, const float* __restrict__ W_all_b,
    const float* __restrict__ W_d,   const float* __restrict__ W_d_b,
    float* __restrict__ feat)
{
    extern __shared__ char smc[];
    uint64_t* Wsm = (uint64_t*)(smc + S2_WOFF);
    float*    P   = (float*)(smc + S2_POFF);
    float*    Bi  = (float*)(smc + S2_BOFF);

    const int tid    = threadIdx.x;
    const int bh     = blockIdx.x & 1;
    const int j0     = (blockIdx.x >> 1) * 4;
    const int b_base = bh * 64;

    // ---- stage weights (once), duplicated into f32x2 pairs ----
    for (int idx = tid; idx < 5120; idx += 512) {
        int k = idx / 20, r = idx % 20;
        int j = r / 5, g = r % 5;
        float v = (g < 4) ? W_all[k * 1024 + g * 256 + j0 + j]
                          : W_d[k * 256 + j0 + j];
        Wsm[(k * 4 + j) * 5 + g] = pk2(v, v);
    }
    if (tid < 20) {
        int j = tid / 5, g = tid % 5;
        Bi[tid] = (g < 4) ? W_all_b[g * 256 + j0 + j] : W_d_b[j0 + j];
    }
    // zero h0/c0 (parity-0 buffers)
    {
        float* hc0 = &g_hc[0][0][0];
        for (int idx = blockIdx.x * 512 + tid; idx < 2 * HID * BATCH;
             idx += SC2_NBLK * 512)
            hc0[idx] = 0.f;
    }
    grid_barrier(1);

    const int warp = tid >> 5, lane = tid & 31;
    const int jp = lane >> 4;          // feature pair 0/1
    const int bq = lane & 15;          // 4-batch quad
    const int b  = b_base + bq * 4;
    const int kbeg = warp * 16;

    for (int t = 0; t < SEQ; t++) {
        const float* hT = &g_hc[t & 1][0][0];
        const float* cT = &g_hc[t & 1][1][0];

        uint64_t acc2[2][5][2];
#pragma unroll
        for (int jj = 0; jj < 2; jj++)
#pragma unroll
            for (int g = 0; g < 5; g++) {
                acc2[jj][g][0] = 0ull;
                acc2[jj][g][1] = 0ull;
            }

#pragma unroll 4
        for (int kk = 0; kk < 16; kk++) {
            int k = kbeg + kk;
            float4 h4 = *(const float4*)(hT + k * 128 + b);
            float4 c4 = *(const float4*)(cT + k * 128 + b);
            uint64_t hp0 = pk2(h4.x, h4.y), hp1 = pk2(h4.z, h4.w);
            uint64_t cp0 = pk2(c4.x, c4.y), cp1 = pk2(c4.z, c4.w);
#pragma unroll
            for (int jj = 0; jj < 2; jj++) {
                const uint64_t* wr = Wsm + ((size_t)(k * 4 + jp * 2 + jj)) * 5;
                uint64_t w0 = wr[0], w1 = wr[1], w2 = wr[2], w3 = wr[3], w4 = wr[4];
                acc2[jj][0][0] = ffma2(hp0, w0, acc2[jj][0][0]);
                acc2[jj][0][1] = ffma2(hp1, w0, acc2[jj][0][1]);
                acc2[jj][1][0] = ffma2(hp0, w1, acc2[jj][1][0]);
                acc2[jj][1][1] = ffma2(hp1, w1, acc2[jj][1][1]);
                acc2[jj][2][0] = ffma2(hp0, w2, acc2[jj][2][0]);
                acc2[jj][2][1] = ffma2(hp1, w2, acc2[jj][2][1]);
                acc2[jj][3][0] = ffma2(hp0, w3, acc2[jj][3][0]);
                acc2[jj][3][1] = ffma2(hp1, w3, acc2[jj][3][1]);
                acc2[jj][4][0] = ffma2(cp0, w4, acc2[jj][4][0]);
                acc2[jj][4][1] = ffma2(cp1, w4, acc2[jj][4][1]);
            }
        }

        // ---- dump partials: P[(warp*4 + j)*5 + g][64 b], STS.128 ----
#pragma unroll
        for (int jj = 0; jj < 2; jj++)
#pragma unroll
            for (int g = 0; g < 5; g++) {
                float2 lo = upk2(acc2[jj][g][0]);
                float2 hi = upk2(acc2[jj][g][1]);
                *(float4*)&P[((warp * 4 + jp * 2 + jj) * 5 + g) * 64 + bq * 4] =
                    make_float4(lo.x, lo.y, hi.x, hi.y);
            }
        __syncthreads();

        // ---- reduction + pointwise: 256 threads = (4 j) x (64 b) ----
        if (tid < 256) {
            int jj = tid >> 6, bl = tid & 63;
            int jg = j0 + jj;
            int bg = b_base + bl;
            float s[5];
#pragma unroll
            for (int g = 0; g < 5; g++) s[g] = Bi[jj * 5 + g];
#pragma unroll
            for (int q = 0; q < 16; q++) {
#pragma unroll
                for (int g = 0; g < 5; g++)
                    s[g] += P[((q * 4 + jj) * 5 + g) * 64 + bl];
            }
            const float* up = g_utr + ((size_t)t * 1024 + jg) * 128 + bg;
            float f  = sigf(s[0] + up[0 * 256 * 128]);
            float ii = sigf(s[1] + up[1 * 256 * 128]);
            float o  = sigf(s[2] + up[2 * 256 * 128]);
            float ct = sigf(s[3] + up[3 * 256 * 128]);
            float d  = tanhf(s[4]);
            float tt = ts[bg * SEQ + t];
            float cprev = cT[jg * 128 + bg];
            float c_adj = (cprev - d) + d * tt;
            float cn = f * c_adj + ii * ct;
            float hn = o * tanhf(cn);
            g_hc[(t + 1) & 1][0][jg * 128 + bg] = hn;
            g_hc[(t + 1) & 1][1][jg * 128 + bg] = cn;
            feat[((size_t)bg * SEQ + t) * HID + jg] = hn;
        }
        grid_barrier((unsigned)(t + 2));
    }
}

// ---------------- classifier ----------------------------------------------
__global__ void cls_kernel(const float* __restrict__ feat,
                           const float* __restrict__ w,
                           const float* __restrict__ bias,
                           float* __restrict__ out)
{
    int lane = threadIdx.x & 31;
    int wrow = (blockIdx.x * blockDim.x + threadIdx.x) >> 5;
    if (wrow >= MROWS) return;
    const float* fr = feat + (size_t)wrow * HID;
    float s = 0.f;
#pragma unroll
    for (int i = 0; i < 8; i++) s += fr[lane + 32 * i] * w[lane + 32 * i];
#pragma unroll
    for (int off = 16; off > 0; off >>= 1)
        s += __shfl_down_sync(0xffffffffu, s, off);
    if (lane == 0) out[wrow] = s + bias[0];
}

// ---------------------------------------------------------------------------
extern "C" void kernel_launch(void* const* d_in, const int* in_sizes, int n_in,
                              void* d_out, int out_size)
{
    const float* x       = (const float*)d_in[0];
    const float* stages  = (const float*)d_in[1];
    const float* tsmp    = (const float*)d_in[2];
    const float* se_w1   = (const float*)d_in[3];
    const float* se_b1   = (const float*)d_in[4];
    const float* se_w2   = (const float*)d_in[5];
    const float* se_b2   = (const float*)d_in[6];
    const float* se_w3   = (const float*)d_in[7];
    const float* se_b3   = (const float*)d_in[8];
    const float* W_all_w = (const float*)d_in[9];
    const float* W_all_b = (const float*)d_in[10];
    const float* U_all_w = (const float*)d_in[11];
    const float* U_all_b = (const float*)d_in[12];
    const float* W_d_w   = (const float*)d_in[13];
    const float* W_d_b   = (const float*)d_in[14];
    const float* cls_w   = (const float*)d_in[15];
    const float* cls_b   = (const float*)d_in[16];

    float* out  = (float*)d_out;
    float* feat = out + MROWS;

    void *p_st1, *p_st2, *p_st3, *p_u, *p_w2t, *p_w3t, *p_uT;
    cudaGetSymbolAddress(&p_st1, g_st1);
    cudaGetSymbolAddress(&p_st2, g_st2);
    cudaGetSymbolAddress(&p_st3, g_st3);
    cudaGetSymbolAddress(&p_u,   g_u);
    cudaGetSymbolAddress(&p_w2t, g_w2t);
    cudaGetSymbolAddress(&p_w3t, g_w3t);
    cudaGetSymbolAddress(&p_uT,  g_uT);
    float* st1 = (float*)p_st1;
    float* st2 = (float*)p_st2;
    float* st3 = (float*)p_st3;
    float* u   = (float*)p_u;
    float* w2t = (float*)p_w2t;
    float* w3t = (float*)p_w3t;
    float* uT  = (float*)p_uT;

    cudaFuncSetAttribute(tc_gemm_kernel,
                         cudaFuncAttributeMaxDynamicSharedMemorySize, MMA_SMEM);
    cudaFuncSetAttribute(scan2_kernel,
                         cudaFuncAttributeMaxDynamicSharedMemorySize, S2_SMEM);

    // 1. transpose weights to K-major
    wtrans_kernel<<<dim3(32, 64, 3), dim3(32, 8)>>>(se_w2, se_w3, U_all_w);
    // 2. barrier reset
    barinit_kernel<<<1, 1>>>();
    // 3. se1 (K=67) SIMT
    sgemm_kernel<<<dim3(2, 256), 256>>>(stages, se_w1, se_b1, st1,
                                        MROWS, 256, 67, 1);
    // 4. se2
    tc_gemm_kernel<<<dim3(4, 256), 256, MMA_SMEM>>>(
        st1, 256, st1, 256, w2t, se_b2, st2, MROWS, 512, 256, 1);
    // 5. se3
    tc_gemm_kernel<<<dim3(8, 256), 256, MMA_SMEM>>>(
        st2, 512, st2, 512, w3t, se_b3, st3, MROWS, 1024, 512, 1);
    // 6. uproj fused K=2048
    tc_gemm_kernel<<<dim3(8, 256), 256, MMA_SMEM>>>(
        x, 1024, st3, 1024, uT, U_all_b, u, MROWS, 1024, 2048, 0);
    // 7. transpose u to [t][col][b]
    transpose_u_kernel<<<dim3(32, 256, 4), dim3(32, 8)>>>(u);
    // 8. persistent scan v2 (SIMT + f32x2)
    scan2_kernel<<<SC2_NBLK, 512, S2_SMEM>>>(tsmp, W_all_w, W_all_b,
                                             W_d_w, W_d_b, feat);
    // 9. classifier
    cls_kernel<<<4096, 256>>>(feat, cls_w, cls_b, out);
}

// round 8
// speedup vs baseline: 1.9779x; 1.3606x over previous
#include <cuda_runtime.h>
#include <cuda_fp16.h>
#include <math.h>
#include <stdint.h>

#define BATCH 128
#define SEQ   256
#define HID   256
#define MROWS 32768
#define SC2_NBLK 128

// ---------------- scratch (no allocations allowed) ----------------
__device__ __half g_xh  [(size_t)MROWS * 1024];   // x in fp16
__device__ __half g_st1h[(size_t)MROWS * 256];
__device__ __half g_st2h[(size_t)MROWS * 512];
__device__ __half g_st3h[(size_t)MROWS * 1024];
__device__ float  g_u   [(size_t)MROWS * 1024];
__device__ float  g_utr [(size_t)MROWS * 1024];   // [t][col][b]
__device__ float  g_hc[2][2][HID * BATCH];        // [buf][h/c][k*128+b]
__device__ __half g_w2t[512 * 256];               // se_w2^T fp16
__device__ __half g_w3t[1024 * 512];              // se_w3^T fp16
__device__ __half g_uT [1024 * 2048];             // U_all_w^T fp16
__device__ unsigned g_bar_count;
__device__ unsigned g_bar_gen;

// ============================ PTX helpers ==================================
__device__ __forceinline__ uint32_t smem_u32(const void* p) {
    uint32_t a;
    asm("{ .reg .u64 t; cvta.to.shared.u64 t, %1; cvt.u32.u64 %0, t; }"
        : "=r"(a) : "l"(p));
    return a;
}
#define CP_ASYNC16(dst, src) \
    asm volatile("cp.async.cg.shared.global [%0], [%1], 16;" \
                 :: "r"(dst), "l"(src) : "memory")
#define CP_ASYNC_COMMIT() asm volatile("cp.async.commit_group;" ::: "memory")
#define CP_ASYNC_WAIT(n)  asm volatile("cp.async.wait_group %0;" ::"n"(n):"memory")

#define LDMX4(r, a) \
    asm volatile("ldmatrix.sync.aligned.m8n8.x4.shared.b16 {%0,%1,%2,%3}, [%4];" \
        : "=r"((r)[0]), "=r"((r)[1]), "=r"((r)[2]), "=r"((r)[3]) : "r"(a))
#define MMA_F16(d, a, b) \
    asm volatile("mma.sync.aligned.m16n8k16.row.col.f32.f16.f16.f32 " \
        "{%0,%1,%2,%3},{%4,%5,%6,%7},{%8,%9},{%0,%1,%2,%3};" \
        : "+f"((d)[0]), "+f"((d)[1]), "+f"((d)[2]), "+f"((d)[3]) \
        : "r"((a)[0]), "r"((a)[1]), "r"((a)[2]), "r"((a)[3]), \
          "r"((b)[0]), "r"((b)[1]))

__device__ __forceinline__ uint32_t swz128(uint32_t off) {
    return off ^ ((off >> 3) & 0x70);
}
// packed f32x2 (Blackwell base, not arch-'a'-gated)
__device__ __forceinline__ uint64_t pk2(float lo, float hi) {
    uint64_t r;
    asm("mov.b64 %0, {%1, %2};" : "=l"(r) : "f"(lo), "f"(hi));
    return r;
}
__device__ __forceinline__ float2 upk2(uint64_t v) {
    float2 f;
    asm("mov.b64 {%0, %1}, %2;" : "=f"(f.x), "=f"(f.y) : "l"(v));
    return f;
}
__device__ __forceinline__ uint64_t ffma2(uint64_t a, uint64_t b, uint64_t c) {
    uint64_t d;
    asm("fma.rn.f32x2 %0, %1, %2, %3;" : "=l"(d) : "l"(a), "l"(b), "l"(c));
    return d;
}

// ================= fp16 mma.sync GEMM: C[M,N] = [A1|A2] @ BT^T =============
// A1/A2: fp16 [M,K*] row-major (concat along K). BT: fp16 [N,Ktot] K-major.
// CTA tile 128x128, BK=64, 8 warps (2M x 4N), 3-stage cp.async pipeline.
// Out: float (Cf) or fp16 (Ch) selected by Ch != nullptr.
#define STAGES 3
#define STG_BYTES 32768                  // A 16KB + B 16KB
#define HG_SMEM (STAGES * STG_BYTES)     // 96 KB

__global__ __launch_bounds__(256, 2)
void hgemm_kernel(const __half* __restrict__ A1, int K1,
                  const __half* __restrict__ A2, int K2,
                  const __half* __restrict__ BT,
                  const float* __restrict__ bias,
                  float* __restrict__ Cf, __half* __restrict__ Ch,
                  int M, int N, int Ktot, int relu)
{
    extern __shared__ char smc[];
    const uint32_t sbase = smem_u32(smc);
    const int tid  = threadIdx.x;
    const int wid  = tid >> 5, lane = tid & 31;
    const int n0   = blockIdx.x * 128;
    const int m0   = blockIdx.y * 128;
    const int NCH  = Ktot >> 6;
    const int wm   = wid & 1;
    const int wn   = wid >> 1;

    float acc[4][4][4];
#pragma unroll
    for (int mt = 0; mt < 4; mt++)
#pragma unroll
        for (int nt = 0; nt < 4; nt++)
#pragma unroll
            for (int q = 0; q < 4; q++) acc[mt][nt][q] = 0.f;

    auto load_chunk = [&](int stage, int k0) {
        uint32_t sA = sbase + stage * STG_BYTES;
        uint32_t sB = sA + 16384;
        const __half* Ak; int kl;
        if (k0 < K1) { Ak = A1 + k0; kl = K1; }
        else         { Ak = A2 + (k0 - K1); kl = K2; }
#pragma unroll
        for (int q = 0; q < 4; q++) {
            int u = tid + 256 * q;
            int r = u >> 3, c = (u & 7) << 4;
            CP_ASYNC16(sA + swz128((uint32_t)(r * 128 + c)),
                       (const char*)(Ak + (size_t)(m0 + r) * kl) + c);
        }
#pragma unroll
        for (int q = 0; q < 4; q++) {
            int u = tid + 256 * q;
            int r = u >> 3, c = (u & 7) << 4;
            CP_ASYNC16(sB + swz128((uint32_t)(r * 128 + c)),
                       (const char*)(BT + (size_t)(n0 + r) * Ktot + k0) + c);
        }
        CP_ASYNC_COMMIT();
    };

    load_chunk(0, 0);
    load_chunk(1, 64);

    const int arow_l = (lane & 15);
    const int akb_l  = (lane >> 4) << 4;
    const int brow_l = (lane & 7);
    const int bqb_l  = (lane >> 3) << 4;

    for (int i = 0; i < NCH; i++) {
        if (i < NCH - 1) { CP_ASYNC_WAIT(1); }
        else             { CP_ASYNC_WAIT(0); }
        __syncthreads();

        const int j = i + STAGES - 1;
        if (j < NCH) load_chunk(j % STAGES, j * 64);

        uint32_t sA = sbase + (i % STAGES) * STG_BYTES;
        uint32_t sB = sA + 16384;

#pragma unroll
        for (int s32 = 0; s32 < 2; s32++) {
            uint32_t bfr[4][4];
#pragma unroll
            for (int nt = 0; nt < 4; nt++) {
                int row = wn * 32 + nt * 8 + brow_l;
                LDMX4(bfr[nt], sB + swz128((uint32_t)(row * 128 + s32 * 64 + bqb_l)));
            }
#pragma unroll
            for (int kh = 0; kh < 2; kh++) {
#pragma unroll
                for (int mt = 0; mt < 4; mt++) {
                    uint32_t afr[4];
                    int row = wm * 64 + mt * 16 + arow_l;
                    LDMX4(afr, sA + swz128((uint32_t)(row * 128 + s32 * 64 + kh * 32 + akb_l)));
#pragma unroll
                    for (int nt = 0; nt < 4; nt++)
                        MMA_F16(acc[mt][nt], afr, &bfr[nt][kh * 2]);
                }
            }
        }
        __syncthreads();
    }

    const int mbase = m0 + wm * 64;
    const int nbase = n0 + wn * 32;
    const int cc = (lane & 3) * 2;
    const int rr = lane >> 2;
    float bx[4], by[4];
#pragma unroll
    for (int nt = 0; nt < 4; nt++) {
        bx[nt] = bias[nbase + nt * 8 + cc];
        by[nt] = bias[nbase + nt * 8 + cc + 1];
    }
#pragma unroll
    for (int mt = 0; mt < 4; mt++) {
        int r0 = mbase + mt * 16 + rr;
#pragma unroll
        for (int nt = 0; nt < 4; nt++) {
            int c0 = nbase + nt * 8 + cc;
            float v0 = acc[mt][nt][0] + bx[nt];
            float v1 = acc[mt][nt][1] + by[nt];
            float v2 = acc[mt][nt][2] + bx[nt];
            float v3 = acc[mt][nt][3] + by[nt];
            if (relu) {
                v0 = fmaxf(v0, 0.f); v1 = fmaxf(v1, 0.f);
                v2 = fmaxf(v2, 0.f); v3 = fmaxf(v3, 0.f);
            }
            if (Ch) {
                *(__half2*)(Ch + (size_t)r0 * N + c0) = __floats2half2_rn(v0, v1);
                *(__half2*)(Ch + (size_t)(r0 + 8) * N + c0) = __floats2half2_rn(v2, v3);
            } else {
                *(float2*)(Cf + (size_t)r0 * N + c0) = make_float2(v0, v1);
                *(float2*)(Cf + (size_t)(r0 + 8) * N + c0) = make_float2(v2, v3);
            }
        }
    }
}

// ---------------- weight transposes (fp16 out) + barrier init --------------
__global__ void wtrans_kernel(const float* __restrict__ w2,
                              const float* __restrict__ w3,
                              const float* __restrict__ uw)
{
    if (blockIdx.x == 0 && blockIdx.y == 0 && blockIdx.z == 0 &&
        threadIdx.x == 0 && threadIdx.y == 0) {
        g_bar_count = 0u;
        g_bar_gen = 0u;
    }
    const float* in; __half* out; int R, C;
    if (blockIdx.z == 0)      { in = w2; out = g_w2t; R = 256;  C = 512;  }
    else if (blockIdx.z == 1) { in = w3; out = g_w3t; R = 512;  C = 1024; }
    else                      { in = uw; out = g_uT;  R = 2048; C = 1024; }
    if ((int)blockIdx.x * 32 >= C || (int)blockIdx.y * 32 >= R) return;
    __shared__ float t[32][33];
    const int tx = threadIdx.x, ty = threadIdx.y;
#pragma unroll
    for (int i = 0; i < 4; i++) {
        int r = blockIdx.y * 32 + ty + i * 8;
        int c = blockIdx.x * 32 + tx;
        t[ty + i * 8][tx] = in[(size_t)r * C + c];
    }
    __syncthreads();
#pragma unroll
    for (int i = 0; i < 4; i++) {
        int c = blockIdx.x * 32 + ty + i * 8;
        int r = blockIdx.y * 32 + tx;
        out[(size_t)c * R + r] = __float2half_rn(t[tx][ty + i * 8]);
    }
}

// ---------------- x -> fp16 conversion -------------------------------------
__global__ void convx_kernel(const float* __restrict__ x)
{
    size_t i = ((size_t)blockIdx.x * 512 + threadIdx.x) * 4;
    float4 v = *(const float4*)(x + i);
    *(__half2*)(&g_xh[i])     = __floats2half2_rn(v.x, v.y);
    *(__half2*)(&g_xh[i + 2]) = __floats2half2_rn(v.z, v.w);
}

// ---------------- SIMT SGEMM (se1 only, K=67, fp16 out) --------------------
__global__ __launch_bounds__(256, 2) void sgemm_kernel(
    const float* __restrict__ A, const float* __restrict__ B,
    const float* __restrict__ bias, __half* __restrict__ C,
    int M, int N, int K, int relu)
{
    __shared__ float As[8][128];
    __shared__ float Bs[8][128];
    const int tid = threadIdx.x;
    const int tx = tid & 15, ty = tid >> 4;
    const float* Ab = A + (size_t)blockIdx.y * 128 * K;
    const float* Bb = B + blockIdx.x * 128;

    float acc[8][8];
#pragma unroll
    for (int i = 0; i < 8; i++)
#pragma unroll
        for (int j = 0; j < 8; j++) acc[i][j] = 0.f;

    const int aRow = tid >> 1, aCol = (tid & 1) << 2;
    const int bRow = tid >> 5, bCol = (tid & 31) << 2;

    for (int k0 = 0; k0 < K; k0 += 8) {
#pragma unroll
        for (int i2 = 0; i2 < 4; i2++) {
            int kk = aCol + i2;
            As[kk][aRow] = (k0 + kk < K) ? Ab[(size_t)aRow * K + k0 + kk] : 0.f;
        }
        if (k0 + bRow < K) {
            float4 bv = *(const float4*)(Bb + (size_t)(k0 + bRow) * N + bCol);
            Bs[bRow][bCol + 0] = bv.x; Bs[bRow][bCol + 1] = bv.y;
            Bs[bRow][bCol + 2] = bv.z; Bs[bRow][bCol + 3] = bv.w;
        } else {
            Bs[bRow][bCol + 0] = 0.f; Bs[bRow][bCol + 1] = 0.f;
            Bs[bRow][bCol + 2] = 0.f; Bs[bRow][bCol + 3] = 0.f;
        }
        __syncthreads();
#pragma unroll
        for (int kk = 0; kk < 8; kk++) {
            float av[8], bv[8];
#pragma unroll
            for (int i = 0; i < 8; i++) av[i] = As[kk][ty * 8 + i];
#pragma unroll
            for (int j = 0; j < 8; j++) bv[j] = Bs[kk][tx * 8 + j];
#pragma unroll
            for (int i = 0; i < 8; i++)
#pragma unroll
                for (int j = 0; j < 8; j++)
                    acc[i][j] += av[i] * bv[j];
        }
        __syncthreads();
    }

    const int row0 = blockIdx.y * 128 + ty * 8;
    const int col0 = blockIdx.x * 128 + tx * 8;
#pragma unroll
    for (int i = 0; i < 8; i++) {
        __half* Cp = C + (size_t)(row0 + i) * N + col0;
#pragma unroll
        for (int j = 0; j < 8; j += 2) {
            float v0 = acc[i][j]     + bias[col0 + j];
            float v1 = acc[i][j + 1] + bias[col0 + j + 1];
            if (relu) { v0 = fmaxf(v0, 0.f); v1 = fmaxf(v1, 0.f); }
            *(__half2*)(Cp + j) = __floats2half2_rn(v0, v1);
        }
    }
}

__device__ __forceinline__ void grid_barrier(unsigned gen)
{
    __syncthreads();
    if (threadIdx.x == 0) {
        __threadfence();
        unsigned arrived = atomicAdd(&g_bar_count, 1u) + 1u;
        if (arrived == gen * SC2_NBLK) {
            __threadfence();
            *(volatile unsigned*)&g_bar_gen = gen;
        } else {
            while (*(volatile unsigned*)&g_bar_gen < gen) { __nanosleep(32); }
        }
        __threadfence();
    }
    __syncthreads();
}

__device__ __forceinline__ float sigf(float x) { return 1.f / (1.f + __expf(-x)); }

// ================= persistent TLSTM scan (SIMT + f32x2) ====================
// Prologue: u transpose + weight staging + h0/c0 zero, then 256 steps.
#define S2_WOFF 0                 // Wsm2: uint64 [256*4*5]   = 40960 B
#define S2_POFF 40960             // P:    float  [16*4*5*64] = 81920 B (also transpose tiles)
#define S2_BOFF 122880            // Bi:   float  [20]
#define S2_SMEM 123008

__global__ __launch_bounds__(512, 1) void scan2_kernel(
    const float* __restrict__ u,
    const float* __restrict__ ts,
    const float* __restrict__ W_all, const float* __restrict__ W_all_b,
    const float* __restrict__ W_d,   const float* __restrict__ W_d_b,
    float* __restrict__ feat)
{
    extern __shared__ char smc[];
    uint64_t* Wsm = (uint64_t*)(smc + S2_WOFF);
    float*    P   = (float*)(smc + S2_POFF);
    float*    Bi  = (float*)(smc + S2_BOFF);

    const int tid    = threadIdx.x;
    const int bh     = blockIdx.x & 1;
    const int j0     = (blockIdx.x >> 1) * 4;
    const int b_base = bh * 64;

    // ---- stage weights (once), duplicated into f32x2 pairs ----
    for (int idx = tid; idx < 5120; idx += 512) {
        int k = idx / 20, r = idx % 20;
        int j = r / 5, g = r % 5;
        float v = (g < 4) ? W_all[k * 1024 + g * 256 + j0 + j]
                          : W_d[k * 256 + j0 + j];
        Wsm[(k * 4 + j) * 5 + g] = pk2(v, v);
    }
    if (tid < 20) {
        int j = tid / 5, g = tid % 5;
        Bi[tid] = (g < 4) ? W_all_b[g * 256 + j0 + j] : W_d_b[j0 + j];
    }
    __syncthreads();

    // ---- u transpose: u[(b*SEQ+t)*1024+n] -> g_utr[(t*1024+n)*128+b] ----
    {
        const int tx = tid & 31, ty = (tid >> 5) & 7, slot = tid >> 8;
        float* T = P + slot * (32 * 33);
        for (int it = 0; it < 128; it++) {
            int tileIdx = blockIdx.x * 256 + it * 2 + slot;
            int nt = tileIdx & 31;
            int t  = (tileIdx >> 5) & 255;
            int bt = tileIdx >> 13;
#pragma unroll
            for (int i = 0; i < 4; i++)
                T[(ty + i * 8) * 33 + tx] =
                    u[((size_t)((bt * 32 + ty + i * 8) * SEQ + t)) * 1024 + nt * 32 + tx];
            __syncthreads();
#pragma unroll
            for (int i = 0; i < 4; i++)
                g_utr[((size_t)t * 1024 + nt * 32 + ty + i * 8) * 128 + bt * 32 + tx] =
                    T[tx * 33 + ty + i * 8];
            __syncthreads();
        }
    }

    // zero h0/c0 (parity-0 buffers)
    {
        float* hc0 = &g_hc[0][0][0];
        for (int idx = blockIdx.x * 512 + tid; idx < 2 * HID * BATCH;
             idx += SC2_NBLK * 512)
            hc0[idx] = 0.f;
    }
    grid_barrier(1);

    const int warp = tid >> 5, lane = tid & 31;
    const int jp = lane >> 4;
    const int bq = lane & 15;
    const int b  = b_base + bq * 4;
    const int kbeg = warp * 16;
    const int rjj = tid >> 6, rbl = tid & 63;          // reduction role
    const int rjg = j0 + rjj, rbg = b_base + rbl;

    for (int t = 0; t < SEQ; t++) {
        const float* hT = &g_hc[t & 1][0][0];
        const float* cT = &g_hc[t & 1][1][0];

        // prefetch pointwise operands (independent of h/c) — overlaps FMA
        float pu0 = 0.f, pu1 = 0.f, pu2 = 0.f, pu3 = 0.f, ptt = 0.f, pcp = 0.f;
        if (tid < 256) {
            const float* up = g_utr + ((size_t)t * 1024 + rjg) * 128 + rbg;
            pu0 = __ldg(up + 0 * 256 * 128);
            pu1 = __ldg(up + 1 * 256 * 128);
            pu2 = __ldg(up + 2 * 256 * 128);
            pu3 = __ldg(up + 3 * 256 * 128);
            ptt = __ldg(ts + rbg * SEQ + t);
            pcp = cT[rjg * 128 + rbg];
        }

        uint64_t acc2[2][5][2];
#pragma unroll
        for (int jj = 0; jj < 2; jj++)
#pragma unroll
            for (int g = 0; g < 5; g++) {
                acc2[jj][g][0] = 0ull;
                acc2[jj][g][1] = 0ull;
            }

#pragma unroll 4
        for (int kk = 0; kk < 16; kk++) {
            int k = kbeg + kk;
            float4 h4 = *(const float4*)(hT + k * 128 + b);
            float4 c4 = *(const float4*)(cT + k * 128 + b);
            uint64_t hp0 = pk2(h4.x, h4.y), hp1 = pk2(h4.z, h4.w);
            uint64_t cp0 = pk2(c4.x, c4.y), cp1 = pk2(c4.z, c4.w);
#pragma unroll
            for (int jj = 0; jj < 2; jj++) {
                const uint64_t* wr = Wsm + ((size_t)(k * 4 + jp * 2 + jj)) * 5;
                uint64_t w0 = wr[0], w1 = wr[1], w2 = wr[2], w3 = wr[3], w4 = wr[4];
                acc2[jj][0][0] = ffma2(hp0, w0, acc2[jj][0][0]);
                acc2[jj][0][1] = ffma2(hp1, w0, acc2[jj][0][1]);
                acc2[jj][1][0] = ffma2(hp0, w1, acc2[jj][1][0]);
                acc2[jj][1][1] = ffma2(hp1, w1, acc2[jj][1][1]);
                acc2[jj][2][0] = ffma2(hp0, w2, acc2[jj][2][0]);
                acc2[jj][2][1] = ffma2(hp1, w2, acc2[jj][2][1]);
                acc2[jj][3][0] = ffma2(hp0, w3, acc2[jj][3][0]);
                acc2[jj][3][1] = ffma2(hp1, w3, acc2[jj][3][1]);
                acc2[jj][4][0] = ffma2(cp0, w4, acc2[jj][4][0]);
                acc2[jj][4][1] = ffma2(cp1, w4, acc2[jj][4][1]);
            }
        }

#pragma unroll
        for (int jj = 0; jj < 2; jj++)
#pragma unroll
            for (int g = 0; g < 5; g++) {
                float2 lo = upk2(acc2[jj][g][0]);
                float2 hi = upk2(acc2[jj][g][1]);
                *(float4*)&P[((warp * 4 + jp * 2 + jj) * 5 + g) * 64 + bq * 4] =
                    make_float4(lo.x, lo.y, hi.x, hi.y);
            }
        __syncthreads();

        if (tid < 256) {
            float s[5];
#pragma unroll
            for (int g = 0; g < 5; g++) s[g] = Bi[rjj * 5 + g];
#pragma unroll
            for (int q = 0; q < 16; q++) {
#pragma unroll
                for (int g = 0; g < 5; g++)
                    s[g] += P[((q * 4 + rjj) * 5 + g) * 64 + rbl];
            }
            float f  = sigf(s[0] + pu0);
            float ii = sigf(s[1] + pu1);
            float o  = sigf(s[2] + pu2);
            float ct = sigf(s[3] + pu3);
            float d  = tanhf(s[4]);
            float c_adj = (pcp - d) + d * ptt;
            float cn = f * c_adj + ii * ct;
            float hn = o * tanhf(cn);
            g_hc[(t + 1) & 1][0][rjg * 128 + rbg] = hn;
            g_hc[(t + 1) & 1][1][rjg * 128 + rbg] = cn;
            feat[((size_t)rbg * SEQ + t) * HID + rjg] = hn;
        }
        grid_barrier((unsigned)(t + 2));
    }
}

// ---------------- classifier ----------------------------------------------
__global__ void cls_kernel(const float* __restrict__ feat,
                           const float* __restrict__ w,
                           const float* __restrict__ bias,
                           float* __restrict__ out)
{
    int lane = threadIdx.x & 31;
    int wrow = (blockIdx.x * blockDim.x + threadIdx.x) >> 5;
    if (wrow >= MROWS) return;
    const float* fr = feat + (size_t)wrow * HID;
    float s = 0.f;
#pragma unroll
    for (int i = 0; i < 8; i++) s += fr[lane + 32 * i] * w[lane + 32 * i];
#pragma unroll
    for (int off = 16; off > 0; off >>= 1)
        s += __shfl_down_sync(0xffffffffu, s, off);
    if (lane == 0) out[wrow] = s + bias[0];
}

// ---------------------------------------------------------------------------
extern "C" void kernel_launch(void* const* d_in, const int* in_sizes, int n_in,
                              void* d_out, int out_size)
{
    const float* x       = (const float*)d_in[0];
    const float* stages  = (const float*)d_in[1];
    const float* tsmp    = (const float*)d_in[2];
    const float* se_w1   = (const float*)d_in[3];
    const float* se_b1   = (const float*)d_in[4];
    const float* se_w2   = (const float*)d_in[5];
    const float* se_b2   = (const float*)d_in[6];
    const float* se_w3   = (const float*)d_in[7];
    const float* se_b3   = (const float*)d_in[8];
    const float* W_all_w = (const float*)d_in[9];
    const float* W_all_b = (const float*)d_in[10];
    const float* U_all_w = (const float*)d_in[11];
    const float* U_all_b = (const float*)d_in[12];
    const float* W_d_w   = (const float*)d_in[13];
    const float* W_d_b   = (const float*)d_in[14];
    const float* cls_w   = (const float*)d_in[15];
    const float* cls_b   = (const float*)d_in[16];

    float* out  = (float*)d_out;
    float* feat = out + MROWS;

    void *p_st1, *p_st2, *p_st3, *p_u, *p_w2t, *p_w3t, *p_uT;
    cudaGetSymbolAddress(&p_st1, g_st1h);
    cudaGetSymbolAddress(&p_st2, g_st2h);
    cudaGetSymbolAddress(&p_st3, g_st3h);
    cudaGetSymbolAddress(&p_u,   g_u);
    cudaGetSymbolAddress(&p_w2t, g_w2t);
    cudaGetSymbolAddress(&p_w3t, g_w3t);
    cudaGetSymbolAddress(&p_uT,  g_uT);
    __half* st1h = (__half*)p_st1;
    __half* st2h = (__half*)p_st2;
    __half* st3h = (__half*)p_st3;
    float*  u    = (float*)p_u;
    __half* w2t  = (__half*)p_w2t;
    __half* w3t  = (__half*)p_w3t;
    __half* uT   = (__half*)p_uT;
    void* p_xh;
    cudaGetSymbolAddress(&p_xh, g_xh);
    __half* xh = (__half*)p_xh;

    cudaFuncSetAttribute(hgemm_kernel,
                         cudaFuncAttributeMaxDynamicSharedMemorySize, HG_SMEM);
    cudaFuncSetAttribute(scan2_kernel,
                         cudaFuncAttributeMaxDynamicSharedMemorySize, S2_SMEM);

    // 1. weight transposes (fp16) + barrier init
    wtrans_kernel<<<dim3(32, 64, 3), dim3(32, 8)>>>(se_w2, se_w3, U_all_w);
    // 2. x -> fp16
    convx_kernel<<<16384, 512>>>(x);
    // 3. se1 (K=67) SIMT, fp16 out
    sgemm_kernel<<<dim3(2, 256), 256>>>(stages, se_w1, se_b1, st1h,
                                        MROWS, 256, 67, 1);
    // 4. se2: fp16 mma, K=256
    hgemm_kernel<<<dim3(4, 256), 256, HG_SMEM>>>(
        st1h, 256, st1h, 256, w2t, se_b2, nullptr, st2h, MROWS, 512, 256, 1);
    // 5. se3: K=512
    hgemm_kernel<<<dim3(8, 256), 256, HG_SMEM>>>(
        st2h, 512, st2h, 512, w3t, se_b3, nullptr, st3h, MROWS, 1024, 512, 1);
    // 6. uproj fused: [x | st3] K=2048, fp32 out
    hgemm_kernel<<<dim3(8, 256), 256, HG_SMEM>>>(
        xh, 1024, st3h, 1024, uT, U_all_b, u, nullptr, MROWS, 1024, 2048, 0);
    // 7. persistent scan (u transpose in prologue)
    scan2_kernel<<<SC2_NBLK, 512, S2_SMEM>>>(u, tsmp, W_all_w, W_all_b,
                                             W_d_w, W_d_b, feat);
    // 8. classifier
    cls_kernel<<<4096, 256>>>(feat, cls_w, cls_b, out);
}